// round 2
// baseline (speedup 1.0000x reference)
#include <cuda_runtime.h>
#include <cstddef>

// Problem constants
#define BATCH 8
#define HH 64
#define WW 64
#define CC 256
#define NHEADS 8
#define DPH 32          // dim per head
#define N_PIX (HH * WW) // 4096
#define M_TOT (BATCH * N_PIX)     // 32768 rows for the GEMM
#define N_QKV (3 * CC)            // 768
#define K_DIM CC                  // 256

// Scratch: qkv[M_TOT][768]  (q: cols [0,256), k: [256,512), v: [512,768))
__device__ __align__(16) static float g_qkv[(size_t)M_TOT * N_QKV];

// ---------------------------------------------------------------------------
// Kernel 1: qkv = x @ W^T    (A: [32768,256] K-major, W: [768,256] K-major)
// Classic 128x128x8 tile, 8x8 per thread, 256 threads.
// ---------------------------------------------------------------------------
#define BM 128
#define BN 128
#define BK 8

__global__ __launch_bounds__(256) void qkv_gemm(const float* __restrict__ A,
                                                const float* __restrict__ W,
                                                float* __restrict__ C) {
    __shared__ __align__(16) float As[BK][BM + 4];
    __shared__ __align__(16) float Ws[BK][BN + 4];

    const int t  = threadIdx.x;
    const int bm = blockIdx.y * BM;
    const int bn = blockIdx.x * BN;
    const int tx = t & 15;   // 0..15 -> 8 cols each
    const int ty = t >> 4;   // 0..15 -> 8 rows each

    // cooperative load mapping: 2 threads per row, float4 each
    const int lrow = t >> 1;          // 0..127
    const int lcol = (t & 1) * 4;     // 0 or 4
    const float* Ap = A + (size_t)(bm + lrow) * K_DIM + lcol;
    const float* Wp = W + (size_t)(bn + lrow) * K_DIM + lcol;

    float acc[8][8];
#pragma unroll
    for (int i = 0; i < 8; i++)
#pragma unroll
        for (int j = 0; j < 8; j++) acc[i][j] = 0.f;

    for (int k0 = 0; k0 < K_DIM; k0 += BK) {
        float4 av = *(const float4*)(Ap + k0);
        float4 wv = *(const float4*)(Wp + k0);
        As[lcol + 0][lrow] = av.x;
        As[lcol + 1][lrow] = av.y;
        As[lcol + 2][lrow] = av.z;
        As[lcol + 3][lrow] = av.w;
        Ws[lcol + 0][lrow] = wv.x;
        Ws[lcol + 1][lrow] = wv.y;
        Ws[lcol + 2][lrow] = wv.z;
        Ws[lcol + 3][lrow] = wv.w;
        __syncthreads();

#pragma unroll
        for (int kk = 0; kk < BK; kk++) {
            float4 a0 = *(const float4*)&As[kk][ty * 8];
            float4 a1 = *(const float4*)&As[kk][ty * 8 + 4];
            float4 b0 = *(const float4*)&Ws[kk][tx * 8];
            float4 b1 = *(const float4*)&Ws[kk][tx * 8 + 4];
            float a[8] = {a0.x, a0.y, a0.z, a0.w, a1.x, a1.y, a1.z, a1.w};
            float b[8] = {b0.x, b0.y, b0.z, b0.w, b1.x, b1.y, b1.z, b1.w};
#pragma unroll
            for (int i = 0; i < 8; i++)
#pragma unroll
                for (int j = 0; j < 8; j++)
                    acc[i][j] = fmaf(a[i], b[j], acc[i][j]);
        }
        __syncthreads();
    }

#pragma unroll
    for (int i = 0; i < 8; i++) {
        float* Cp = C + (size_t)(bm + ty * 8 + i) * N_QKV + bn + tx * 8;
        *(float4*)(Cp)     = make_float4(acc[i][0], acc[i][1], acc[i][2], acc[i][3]);
        *(float4*)(Cp + 4) = make_float4(acc[i][4], acc[i][5], acc[i][6], acc[i][7]);
    }
}

// ---------------------------------------------------------------------------
// Kernel 2: dilated local attention.
// One warp per (batch, pixel, head); lane = element of dph (32).
// OOB neighbors: score exactly 0 (zero-padded k), v contribution 0,
// but the softmax denominator still includes exp(0 - max). Matches reference.
// ---------------------------------------------------------------------------
__device__ __forceinline__ void attn_core(const float* __restrict__ qkv,
                                          float* __restrict__ out,
                                          const float q,
                                          const float s_in[9],
                                          const int koff[9],
                                          int obase) {
    float s[9];
#pragma unroll
    for (int jj = 0; jj < 9; jj++) s[jj] = s_in[jj];

    // butterfly-reduce all 9 partial dots (every lane ends with full sums)
#pragma unroll
    for (int off = 16; off >= 1; off >>= 1) {
#pragma unroll
        for (int jj = 0; jj < 9; jj++)
            s[jj] += __shfl_xor_sync(0xffffffffu, s[jj], off);
    }

    const float scale = 0.17677669529663687f;  // 32^-0.5
    float m = -1e30f;
#pragma unroll
    for (int jj = 0; jj < 9; jj++) {
        s[jj] *= scale;
        m = fmaxf(m, s[jj]);
    }
    float p[9];
    float denom = 0.f;
#pragma unroll
    for (int jj = 0; jj < 9; jj++) {
        p[jj] = __expf(s[jj] - m);
        denom += p[jj];
    }
    const float inv = 1.f / denom;

    float o = 0.f;
#pragma unroll
    for (int jj = 0; jj < 9; jj++) {
        if (koff[jj] >= 0)
            o = fmaf(p[jj] * inv, qkv[koff[jj] + CC], o);  // v = k offset + 256
    }
    out[obase] = o;
}

__global__ __launch_bounds__(256) void dilate_attn(const float* __restrict__ qkv,
                                                   float* __restrict__ out) {
    const int lane = threadIdx.x & 31;
    const int w    = blockIdx.x * 8 + (threadIdx.x >> 5);  // global warp id
    const int head = w & 7;
    const int pix  = (w >> 3) & (N_PIX - 1);
    const int b    = w >> 15;                               // / (8*4096)
    const int y    = pix >> 6;
    const int x    = pix & 63;

    const int pbase = (b * N_PIX + pix) * N_QKV + head * DPH + lane;
    const float q   = qkv[pbase];
    const int obase = (b * N_PIX + pix) * CC + head * DPH + lane;

    float s[9];
    int   koff[9];

    if (y >= 3 && y < HH - 3 && x >= 3 && x < WW - 3) {
        // interior fast path: all 9 neighbors valid, no predication
        const int kctr = (b * N_PIX + pix) * N_QKV + CC + head * DPH + lane;
#pragma unroll
        for (int i = 0; i < 3; i++) {
#pragma unroll
            for (int j = 0; j < 3; j++) {
                const int jj = i * 3 + j;
                koff[jj] = kctr + ((i - 1) * 3 * WW + (j - 1) * 3) * N_QKV;
            }
        }
        float kv[9];
#pragma unroll
        for (int jj = 0; jj < 9; jj++) kv[jj] = qkv[koff[jj]];  // batched loads
#pragma unroll
        for (int jj = 0; jj < 9; jj++) s[jj] = q * kv[jj];
        attn_core(qkv, out, q, s, koff, obase);
    } else {
        // boundary path: zero-padded reference semantics
#pragma unroll
        for (int i = 0; i < 3; i++) {
#pragma unroll
            for (int j = 0; j < 3; j++) {
                const int jj = i * 3 + j;
                const int ny = y + (i - 1) * 3;
                const int nx = x + (j - 1) * 3;
                if (ny >= 0 && ny < HH && nx >= 0 && nx < WW) {
                    const int nb = (b * N_PIX + ny * WW + nx) * N_QKV + CC + head * DPH + lane;
                    koff[jj] = nb;
                    s[jj]    = q * qkv[nb];
                } else {
                    koff[jj] = -1;
                    s[jj]    = 0.f;
                }
            }
        }
        attn_core(qkv, out, q, s, koff, obase);
    }
}

// ---------------------------------------------------------------------------
extern "C" void kernel_launch(void* const* d_in, const int* in_sizes, int n_in,
                              void* d_out, int out_size) {
    const float* x = (const float*)d_in[0];
    const float* W = (const float*)d_in[1];
    // defensive: match by size (x has 8.39M elems, W has 196608)
    if (n_in >= 2 && in_sizes[0] == N_QKV * K_DIM) {
        x = (const float*)d_in[1];
        W = (const float*)d_in[0];
    }
    float* out = (float*)d_out;

    float* qkv;
    cudaGetSymbolAddress((void**)&qkv, g_qkv);

    dim3 ggrid(N_QKV / BN, M_TOT / BM);  // (6, 256)
    qkv_gemm<<<ggrid, 256>>>(x, W, qkv);

    const int total_warps = BATCH * N_PIX * NHEADS;  // 262144
    dilate_attn<<<total_warps / 8, 256>>>(qkv, out);
}

// round 5
// speedup vs baseline: 2.2379x; 2.2379x over previous
#include <cuda_runtime.h>
#include <cstdint>
#include <cstddef>

// ---------------------------------------------------------------------------
// Problem constants
// ---------------------------------------------------------------------------
#define BATCH 8
#define HH 64
#define WW 64
#define CC 256
#define NHEADS 8
#define DPH 32
#define N_PIX (HH * WW)            // 4096
#define M_TOT (BATCH * N_PIX)      // 32768
#define N_QKV (3 * CC)             // 768
#define K_DIM CC                   // 256

// GEMM tiling
#define BMT 128                    // block M tile
#define BNT 128                    // block N tile
#define CHK 32                     // K chunk
#define NCHK (K_DIM / CHK)         // 8
#define PAD 36                     // smem row stride (floats): banks (4g+t)%32 distinct

// Scratch: qkv[M_TOT][768]  (q: cols [0,256), k: [256,512), v: [512,768))
__device__ __align__(128) static float g_qkv[(size_t)M_TOT * N_QKV];

// ---------------------------------------------------------------------------
// helpers
// ---------------------------------------------------------------------------
__device__ __forceinline__ uint32_t smem_u32(const void* p) {
    uint32_t a;
    asm("{ .reg .u64 t; cvta.to.shared.u64 t, %1; cvt.u32.u64 %0, t; }" : "=r"(a) : "l"(p));
    return a;
}
__device__ __forceinline__ void cp_async16(uint32_t dst, const float* src) {
    asm volatile("cp.async.cg.shared.global [%0], [%1], 16;" :: "r"(dst), "l"(src) : "memory");
}
#define CP_COMMIT() asm volatile("cp.async.commit_group;" ::: "memory")
#define CP_WAIT(n)  asm volatile("cp.async.wait_group %0;" :: "n"(n) : "memory")

__device__ __forceinline__ uint32_t to_tf32(float x) {
    uint32_t r;
    asm("cvt.rna.tf32.f32 %0, %1;" : "=r"(r) : "f"(x));
    return r;
}
__device__ __forceinline__ void mma_tf32(float c[4], uint32_t a0, uint32_t a1,
                                         uint32_t a2, uint32_t a3,
                                         uint32_t b0, uint32_t b1) {
    asm volatile(
        "mma.sync.aligned.m16n8k8.row.col.f32.tf32.tf32.f32 "
        "{%0,%1,%2,%3}, {%4,%5,%6,%7}, {%8,%9}, {%0,%1,%2,%3};"
        : "+f"(c[0]), "+f"(c[1]), "+f"(c[2]), "+f"(c[3])
        : "r"(a0), "r"(a1), "r"(a2), "r"(a3), "r"(b0), "r"(b1));
}

// ---------------------------------------------------------------------------
// Kernel 1: qkv = x @ W^T  via mma.sync tf32.
// A: [32768,256] K-major. W: [768,256] K-major (so the GEMM is A @ W^T with
// B loaded n-major/k-contig -> col-major fragments).
// Block 128x128, 8 warps (2x4), warp tile 64x32, double-buffered cp.async.
// ---------------------------------------------------------------------------
__global__ __launch_bounds__(256)
void qkv_gemm_mma(const float* __restrict__ A, const float* __restrict__ W,
                  float* __restrict__ Cout) {
    extern __shared__ float sm[];
    float* As = sm;                        // [2][128][PAD]
    float* Bs = sm + 2 * BMT * PAD;        // [2][128][PAD]
    const uint32_t sb  = smem_u32(sm);
    const uint32_t sbB = sb + 2 * BMT * PAD * 4;

    const int tid  = threadIdx.x;
    const int lane = tid & 31;
    const int wid  = tid >> 5;
    const int wm   = (wid & 1) * 64;       // warp m offset within block
    const int wn   = (wid >> 1) * 32;      // warp n offset within block
    const int g    = lane >> 2;            // 0..7
    const int t    = lane & 3;             // 0..3
    const int bm   = blockIdx.y * BMT;
    const int bn   = blockIdx.x * BNT;

    // cooperative chunk loader: A 128x32 floats + B 128x32 floats, 16B units
    auto load_chunk = [&](int kc, int st) {
        const int kb = kc * CHK;
        const int row = tid >> 1;                 // 0..127 (2 thr/row)
        const int seg = (tid & 1) * 4;            // float4 seg 0 or 4
        const uint32_t soff = (uint32_t)(st * BMT * PAD + row * PAD) * 4;
        const float* Ap = A + (size_t)(bm + row) * K_DIM + kb;
        const float* Wp = W + (size_t)(bn + row) * K_DIM + kb;
        cp_async16(sb  + soff + (seg    ) * 16, Ap + seg * 4);
        cp_async16(sb  + soff + (seg + 1) * 16, Ap + seg * 4 + 4);
        cp_async16(sb  + soff + (seg + 2) * 16, Ap + seg * 4 + 8);
        cp_async16(sb  + soff + (seg + 3) * 16, Ap + seg * 4 + 12);
        cp_async16(sbB + soff + (seg    ) * 16, Wp + seg * 4);
        cp_async16(sbB + soff + (seg + 1) * 16, Wp + seg * 4 + 4);
        cp_async16(sbB + soff + (seg + 2) * 16, Wp + seg * 4 + 8);
        cp_async16(sbB + soff + (seg + 3) * 16, Wp + seg * 4 + 12);
    };

    float acc[4][4][4];
#pragma unroll
    for (int i = 0; i < 4; i++)
#pragma unroll
        for (int j = 0; j < 4; j++)
#pragma unroll
            for (int r = 0; r < 4; r++) acc[i][j][r] = 0.f;

    load_chunk(0, 0);
    CP_COMMIT();

    for (int kc = 0; kc < NCHK; kc++) {
        if (kc + 1 < NCHK) { load_chunk(kc + 1, (kc + 1) & 1); CP_COMMIT(); CP_WAIT(1); }
        else               { CP_WAIT(0); }
        __syncthreads();

        const float* Ast = As + (kc & 1) * BMT * PAD;
        const float* Bst = Bs + (kc & 1) * BMT * PAD;

#pragma unroll
        for (int s = 0; s < 4; s++) {              // 4 k-steps of 8
            const int c0 = s * 8;
            uint32_t af[4][4], bf[4][2];
#pragma unroll
            for (int i = 0; i < 4; i++) {
                const int r0 = wm + i * 16;
                af[i][0] = to_tf32(Ast[(r0 + g    ) * PAD + c0 + t    ]);
                af[i][1] = to_tf32(Ast[(r0 + g + 8) * PAD + c0 + t    ]);
                af[i][2] = to_tf32(Ast[(r0 + g    ) * PAD + c0 + t + 4]);
                af[i][3] = to_tf32(Ast[(r0 + g + 8) * PAD + c0 + t + 4]);
            }
#pragma unroll
            for (int j = 0; j < 4; j++) {
                const int n0 = wn + j * 8 + g;
                bf[j][0] = to_tf32(Bst[n0 * PAD + c0 + t    ]);
                bf[j][1] = to_tf32(Bst[n0 * PAD + c0 + t + 4]);
            }
#pragma unroll
            for (int i = 0; i < 4; i++)
#pragma unroll
                for (int j = 0; j < 4; j++)
                    mma_tf32(acc[i][j], af[i][0], af[i][1], af[i][2], af[i][3],
                             bf[j][0], bf[j][1]);
        }
        __syncthreads();
    }

    // Epilogue: c0,c1 at (row, col..col+1), c2,c3 at (row+8, col..col+1)
#pragma unroll
    for (int i = 0; i < 4; i++) {
        const int row = bm + wm + i * 16 + g;
#pragma unroll
        for (int j = 0; j < 4; j++) {
            const int col = bn + wn + j * 8 + 2 * t;
            *(float2*)(Cout + (size_t)row * N_QKV + col) =
                make_float2(acc[i][j][0], acc[i][j][1]);
            *(float2*)(Cout + (size_t)(row + 8) * N_QKV + col) =
                make_float2(acc[i][j][2], acc[i][j][3]);
        }
    }
}

// ---------------------------------------------------------------------------
// Kernel 2: dilated local attention. Warp = 4 (b,pix,head) items, 8 lanes each,
// lane covers 4 channels via float4. OOB neighbors: score 0 in softmax (zero-pad
// reference semantics), v contribution skipped.
// ---------------------------------------------------------------------------
__global__ __launch_bounds__(256) void dilate_attn(const float* __restrict__ qkv,
                                                   float* __restrict__ out) {
    const int lane = threadIdx.x & 31;
    const int wid  = threadIdx.x >> 5;
    const int sub  = lane >> 3;               // item within warp
    const int sl   = lane & 7;                // sub-lane: 4-channel slice
    const int item = (blockIdx.x * 8 + wid) * 4 + sub;
    const int head = item & 7;
    const int pix  = (item >> 3) & (N_PIX - 1);
    const int b    = item >> 15;
    const int y    = pix >> 6;
    const int x    = pix & 63;

    const float4* __restrict__ q4p = (const float4*)qkv;
    const int rowb = (b * N_PIX + pix) * (N_QKV / 4);       // float4 units
    const int cb   = head * (DPH / 4) + sl;                  // 0..63
    const float4 q4 = q4p[rowb + cb];

    float s[9];
    int   koff[9];     // float4 index of k element, or -1

    if (y >= 3 && y < HH - 3 && x >= 3 && x < WW - 3) {
#pragma unroll
        for (int i = 0; i < 3; i++)
#pragma unroll
            for (int j = 0; j < 3; j++) {
                const int jj = i * 3 + j;
                koff[jj] = rowb + ((i - 1) * 3 * WW + (j - 1) * 3) * (N_QKV / 4)
                           + (CC / 4) + cb;
            }
        float4 kv[9];
#pragma unroll
        for (int jj = 0; jj < 9; jj++) kv[jj] = q4p[koff[jj]];
#pragma unroll
        for (int jj = 0; jj < 9; jj++)
            s[jj] = fmaf(q4.x, kv[jj].x, fmaf(q4.y, kv[jj].y,
                    fmaf(q4.z, kv[jj].z, q4.w * kv[jj].w)));
    } else {
#pragma unroll
        for (int i = 0; i < 3; i++)
#pragma unroll
            for (int j = 0; j < 3; j++) {
                const int jj = i * 3 + j;
                const int ny = y + (i - 1) * 3;
                const int nx = x + (j - 1) * 3;
                if (ny >= 0 && ny < HH && nx >= 0 && nx < WW) {
                    const int nb = (b * N_PIX + ny * WW + nx) * (N_QKV / 4) + (CC / 4) + cb;
                    koff[jj] = nb;
                    const float4 kv = q4p[nb];
                    s[jj] = fmaf(q4.x, kv.x, fmaf(q4.y, kv.y, fmaf(q4.z, kv.z, q4.w * kv.w)));
                } else {
                    koff[jj] = -1;
                    s[jj] = 0.f;
                }
            }
    }

    // reduce over the 8-lane group (xor 4,2,1 stays in-group)
#pragma unroll
    for (int off = 4; off >= 1; off >>= 1)
#pragma unroll
        for (int jj = 0; jj < 9; jj++)
            s[jj] += __shfl_xor_sync(0xffffffffu, s[jj], off);

    const float scale = 0.17677669529663687f;   // 32^-0.5
    float m = -1e30f;
#pragma unroll
    for (int jj = 0; jj < 9; jj++) { s[jj] *= scale; m = fmaxf(m, s[jj]); }
    float denom = 0.f;
    float p[9];
#pragma unroll
    for (int jj = 0; jj < 9; jj++) { p[jj] = __expf(s[jj] - m); denom += p[jj]; }
    const float inv = 1.f / denom;

    float4 o = make_float4(0.f, 0.f, 0.f, 0.f);
#pragma unroll
    for (int jj = 0; jj < 9; jj++) {
        if (koff[jj] >= 0) {
            const float4 v = q4p[koff[jj] + (CC / 4)];   // v = k + 256 floats
            const float wj = p[jj] * inv;
            o.x = fmaf(wj, v.x, o.x);
            o.y = fmaf(wj, v.y, o.y);
            o.z = fmaf(wj, v.z, o.z);
            o.w = fmaf(wj, v.w, o.w);
        }
    }
    ((float4*)out)[(b * N_PIX + pix) * (CC / 4) + cb] = o;
}

// ---------------------------------------------------------------------------
extern "C" void kernel_launch(void* const* d_in, const int* in_sizes, int n_in,
                              void* d_out, int out_size) {
    const float* x = (const float*)d_in[0];
    const float* W = (const float*)d_in[1];
    if (n_in >= 2 && in_sizes[0] == N_QKV * K_DIM) {   // defensive order check
        x = (const float*)d_in[1];
        W = (const float*)d_in[0];
    }
    float* out = (float*)d_out;

    float* qkv;
    cudaGetSymbolAddress((void**)&qkv, g_qkv);

    const int smem_bytes = 4 * BMT * PAD * 4;           // 73728
    cudaFuncSetAttribute(qkv_gemm_mma, cudaFuncAttributeMaxDynamicSharedMemorySize,
                         smem_bytes);
    dim3 ggrid(N_QKV / BNT, M_TOT / BMT);               // (6, 256)
    qkv_gemm_mma<<<ggrid, 256, smem_bytes>>>(x, W, qkv);

    const int items = BATCH * N_PIX * NHEADS;           // 262144
    dilate_attn<<<items / 32, 256>>>(qkv, out);         // 4 items/warp, 8 warps/block
}

// round 8
// speedup vs baseline: 2.7112x; 1.2115x over previous
#include <cuda_runtime.h>
#include <cstdint>
#include <cstddef>

// ---------------------------------------------------------------------------
// Problem constants
// ---------------------------------------------------------------------------
#define BATCH 8
#define HH 64
#define WW 64
#define CC 256
#define NHEADS 8
#define DPH 32
#define N_PIX (HH * WW)            // 4096
#define M_TOT (BATCH * N_PIX)      // 32768
#define N_QKV (3 * CC)             // 768
#define K_DIM CC                   // 256

// GEMM tiling: block 128x128, 4 warps (2x2), warp tile 64x64
#define BMT 128
#define BNT 128
#define CHK 32
#define NCHK (K_DIM / CHK)         // 8
#define PAD 36                     // smem row stride (floats): banks (4g+t)%32 distinct
#define A_TILE (BMT * PAD)         // 4608 floats per stage
#define B_TILE (BNT * PAD)         // 4608 floats per stage
#define NTHR 128

// Scratch: qkv[M_TOT][768]  (q: cols [0,256), k: [256,512), v: [512,768))
__device__ __align__(128) static float g_qkv[(size_t)M_TOT * N_QKV];

// ---------------------------------------------------------------------------
// helpers
// ---------------------------------------------------------------------------
__device__ __forceinline__ uint32_t smem_u32(const void* p) {
    uint32_t a;
    asm("{ .reg .u64 t; cvta.to.shared.u64 t, %1; cvt.u32.u64 %0, t; }" : "=r"(a) : "l"(p));
    return a;
}
__device__ __forceinline__ void cp_async16(uint32_t dst, const float* src) {
    asm volatile("cp.async.cg.shared.global [%0], [%1], 16;" :: "r"(dst), "l"(src) : "memory");
}
#define CP_COMMIT() asm volatile("cp.async.commit_group;" ::: "memory")
#define CP_WAIT(n)  asm volatile("cp.async.wait_group %0;" :: "n"(n) : "memory")

__device__ __forceinline__ float to_tf32_f(float x) {
    uint32_t r;
    asm("cvt.rna.tf32.f32 %0, %1;" : "=r"(r) : "f"(x));
    return __uint_as_float(r);
}
__device__ __forceinline__ void mma_tf32(float c[4], uint32_t a0, uint32_t a1,
                                         uint32_t a2, uint32_t a3,
                                         uint32_t b0, uint32_t b1) {
    asm volatile(
        "mma.sync.aligned.m16n8k8.row.col.f32.tf32.tf32.f32 "
        "{%0,%1,%2,%3}, {%4,%5,%6,%7}, {%8,%9}, {%0,%1,%2,%3};"
        : "+f"(c[0]), "+f"(c[1]), "+f"(c[2]), "+f"(c[3])
        : "r"(a0), "r"(a1), "r"(a2), "r"(a3), "r"(b0), "r"(b1));
}

// ---------------------------------------------------------------------------
// Kernel 1: qkv = x @ W^T via mma.sync tf32.
// Block 128x128, 4 warps in 2(m)x2(n), warp tile 64x64, 128 threads.
// Double-buffered cp.async; per-chunk in-place tf32 pre-convert so the inner
// loop is pure LDS + MMA.
// ---------------------------------------------------------------------------
__global__ __launch_bounds__(NTHR)
void qkv_gemm_mma(const float* __restrict__ A, const float* __restrict__ W,
                  float* __restrict__ Cout) {
    extern __shared__ float sm[];
    float* As = sm;                        // [2][128][PAD]
    float* Bs = sm + 2 * A_TILE;           // [2][128][PAD]
    const uint32_t sbA = smem_u32(sm);
    const uint32_t sbB = sbA + 2 * A_TILE * 4;

    const int tid  = threadIdx.x;
    const int lane = tid & 31;
    const int wid  = tid >> 5;             // 0..3
    const int wm   = (wid & 1) * 64;       // warp m offset
    const int wn   = (wid >> 1) * 64;      // warp n offset
    const int g    = lane >> 2;            // 0..7
    const int t    = lane & 3;             // 0..3
    const int bm   = blockIdx.y * BMT;
    const int bn   = blockIdx.x * BNT;

    // cooperative chunk loader: A 128x32 + B 128x32 floats as 16B units
    auto load_chunk = [&](int kc, int st) {
        const int kb = kc * CHK;
#pragma unroll
        for (int it = 0; it < 16; it++) {
            const int u = it * NTHR + tid;               // 0..2047
            if (u < 1024) {
                const int row = u >> 3, seg = u & 7;
                cp_async16(sbA + (uint32_t)(st * A_TILE + row * PAD + seg * 4) * 4,
                           A + (size_t)(bm + row) * K_DIM + kb + seg * 4);
            } else {
                const int u2 = u - 1024;
                const int row = u2 >> 3, seg = u2 & 7;
                cp_async16(sbB + (uint32_t)(st * B_TILE + row * PAD + seg * 4) * 4,
                           W + (size_t)(bn + row) * K_DIM + kb + seg * 4);
            }
        }
    };

    float acc[4][8][4];
#pragma unroll
    for (int i = 0; i < 4; i++)
#pragma unroll
        for (int j = 0; j < 8; j++)
#pragma unroll
            for (int r = 0; r < 4; r++) acc[i][j][r] = 0.f;

    load_chunk(0, 0);
    CP_COMMIT();

    for (int kc = 0; kc < NCHK; kc++) {
        if (kc + 1 < NCHK) { load_chunk(kc + 1, (kc + 1) & 1); CP_COMMIT(); CP_WAIT(1); }
        else               { CP_WAIT(0); }
        __syncthreads();

        float* Ast = As + (kc & 1) * A_TILE;
        float* Bst = Bs + (kc & 1) * B_TILE;

        // in-place tf32 pre-convert: A 1024 + B 1024 float4s over 128 threads
#pragma unroll
        for (int it = 0; it < 8; it++) {
            const int idx = it * NTHR + tid;             // 0..1023
            float4* p = (float4*)&Ast[(idx >> 3) * PAD + (idx & 7) * 4];
            float4 v = *p;
            *p = make_float4(to_tf32_f(v.x), to_tf32_f(v.y), to_tf32_f(v.z), to_tf32_f(v.w));
        }
#pragma unroll
        for (int it = 0; it < 8; it++) {
            const int idx = it * NTHR + tid;             // 0..1023
            float4* p = (float4*)&Bst[(idx >> 3) * PAD + (idx & 7) * 4];
            float4 v = *p;
            *p = make_float4(to_tf32_f(v.x), to_tf32_f(v.y), to_tf32_f(v.z), to_tf32_f(v.w));
        }
        __syncthreads();

        const uint32_t* Au = (const uint32_t*)Ast;
        const uint32_t* Bu = (const uint32_t*)Bst;

#pragma unroll
        for (int s = 0; s < 4; s++) {                    // 4 k-steps of 8
            const int c0 = s * 8;
            uint32_t af[4][4], bf[8][2];
#pragma unroll
            for (int i = 0; i < 4; i++) {
                const int r0 = wm + i * 16;
                af[i][0] = Au[(r0 + g    ) * PAD + c0 + t    ];
                af[i][1] = Au[(r0 + g + 8) * PAD + c0 + t    ];
                af[i][2] = Au[(r0 + g    ) * PAD + c0 + t + 4];
                af[i][3] = Au[(r0 + g + 8) * PAD + c0 + t + 4];
            }
#pragma unroll
            for (int j = 0; j < 8; j++) {
                const int n0 = wn + j * 8 + g;
                bf[j][0] = Bu[n0 * PAD + c0 + t    ];
                bf[j][1] = Bu[n0 * PAD + c0 + t + 4];
            }
#pragma unroll
            for (int i = 0; i < 4; i++)
#pragma unroll
                for (int j = 0; j < 8; j++)
                    mma_tf32(acc[i][j], af[i][0], af[i][1], af[i][2], af[i][3],
                             bf[j][0], bf[j][1]);
        }
        __syncthreads();
    }

    // Epilogue: c0,c1 at (row, col..col+1), c2,c3 at (row+8, ...)
#pragma unroll
    for (int i = 0; i < 4; i++) {
        const int row = bm + wm + i * 16 + g;
#pragma unroll
        for (int j = 0; j < 8; j++) {
            const int col = bn + wn + j * 8 + 2 * t;
            *(float2*)(Cout + (size_t)row * N_QKV + col) =
                make_float2(acc[i][j][0], acc[i][j][1]);
            *(float2*)(Cout + (size_t)(row + 8) * N_QKV + col) =
                make_float2(acc[i][j][2], acc[i][j][3]);
        }
    }
}

// ---------------------------------------------------------------------------
// Kernel 2: dilated local attention. Warp = 4 (b,pix,head) items, 8 lanes each,
// lane covers 4 channels via float4. OOB neighbors: score 0 in softmax (zero-pad
// reference semantics), v contribution skipped.  (Unchanged: 40.4 us measured.)
// ---------------------------------------------------------------------------
__global__ __launch_bounds__(256) void dilate_attn(const float* __restrict__ qkv,
                                                   float* __restrict__ out) {
    const int lane = threadIdx.x & 31;
    const int wid  = threadIdx.x >> 5;
    const int sub  = lane >> 3;               // item within warp
    const int sl   = lane & 7;                // sub-lane: 4-channel slice
    const int item = (blockIdx.x * 8 + wid) * 4 + sub;
    const int head = item & 7;
    const int pix  = (item >> 3) & (N_PIX - 1);
    const int b    = item >> 15;
    const int y    = pix >> 6;
    const int x    = pix & 63;

    const float4* __restrict__ q4p = (const float4*)qkv;
    const int rowb = (b * N_PIX + pix) * (N_QKV / 4);       // float4 units
    const int cb   = head * (DPH / 4) + sl;                  // 0..63
    const float4 q4 = q4p[rowb + cb];

    float s[9];
    int   koff[9];     // float4 index of k element, or -1

    if (y >= 3 && y < HH - 3 && x >= 3 && x < WW - 3) {
#pragma unroll
        for (int i = 0; i < 3; i++)
#pragma unroll
            for (int j = 0; j < 3; j++) {
                const int jj = i * 3 + j;
                koff[jj] = rowb + ((i - 1) * 3 * WW + (j - 1) * 3) * (N_QKV / 4)
                           + (CC / 4) + cb;
            }
        float4 kv[9];
#pragma unroll
        for (int jj = 0; jj < 9; jj++) kv[jj] = q4p[koff[jj]];
#pragma unroll
        for (int jj = 0; jj < 9; jj++)
            s[jj] = fmaf(q4.x, kv[jj].x, fmaf(q4.y, kv[jj].y,
                    fmaf(q4.z, kv[jj].z, q4.w * kv[jj].w)));
    } else {
#pragma unroll
        for (int i = 0; i < 3; i++)
#pragma unroll
            for (int j = 0; j < 3; j++) {
                const int jj = i * 3 + j;
                const int ny = y + (i - 1) * 3;
                const int nx = x + (j - 1) * 3;
                if (ny >= 0 && ny < HH && nx >= 0 && nx < WW) {
                    const int nb = (b * N_PIX + ny * WW + nx) * (N_QKV / 4) + (CC / 4) + cb;
                    koff[jj] = nb;
                    const float4 kv = q4p[nb];
                    s[jj] = fmaf(q4.x, kv.x, fmaf(q4.y, kv.y, fmaf(q4.z, kv.z, q4.w * kv.w)));
                } else {
                    koff[jj] = -1;
                    s[jj] = 0.f;
                }
            }
    }

    // reduce over the 8-lane group (xor 4,2,1 stays in-group)
#pragma unroll
    for (int off = 4; off >= 1; off >>= 1)
#pragma unroll
        for (int jj = 0; jj < 9; jj++)
            s[jj] += __shfl_xor_sync(0xffffffffu, s[jj], off);

    const float scale = 0.17677669529663687f;   // 32^-0.5
    float m = -1e30f;
#pragma unroll
    for (int jj = 0; jj < 9; jj++) { s[jj] *= scale; m = fmaxf(m, s[jj]); }
    float denom = 0.f;
    float p[9];
#pragma unroll
    for (int jj = 0; jj < 9; jj++) { p[jj] = __expf(s[jj] - m); denom += p[jj]; }
    const float inv = 1.f / denom;

    float4 o = make_float4(0.f, 0.f, 0.f, 0.f);
#pragma unroll
    for (int jj = 0; jj < 9; jj++) {
        if (koff[jj] >= 0) {
            const float4 v = q4p[koff[jj] + (CC / 4)];   // v = k + 256 floats
            const float wj = p[jj] * inv;
            o.x = fmaf(wj, v.x, o.x);
            o.y = fmaf(wj, v.y, o.y);
            o.z = fmaf(wj, v.z, o.z);
            o.w = fmaf(wj, v.w, o.w);
        }
    }
    ((float4*)out)[(b * N_PIX + pix) * (CC / 4) + cb] = o;
}

// ---------------------------------------------------------------------------
extern "C" void kernel_launch(void* const* d_in, const int* in_sizes, int n_in,
                              void* d_out, int out_size) {
    const float* x = (const float*)d_in[0];
    const float* W = (const float*)d_in[1];
    if (n_in >= 2 && in_sizes[0] == N_QKV * K_DIM) {   // defensive order check
        x = (const float*)d_in[1];
        W = (const float*)d_in[0];
    }
    float* out = (float*)d_out;

    float* qkv;
    cudaGetSymbolAddress((void**)&qkv, g_qkv);

    const int smem_bytes = (2 * A_TILE + 2 * B_TILE) * 4;   // 73728 (proven size)
    cudaFuncSetAttribute(qkv_gemm_mma, cudaFuncAttributeMaxDynamicSharedMemorySize,
                         smem_bytes);
    dim3 ggrid(N_QKV / BNT, M_TOT / BMT);               // (6, 256)
    qkv_gemm_mma<<<ggrid, NTHR, smem_bytes>>>(x, W, qkv);

    const int items = BATCH * N_PIX * NHEADS;           // 262144
    dilate_attn<<<items / 32, 256>>>(qkv, out);         // 4 items/warp, 8 warps/block
}